// round 2
// baseline (speedup 1.0000x reference)
#include <cuda_runtime.h>

#define FULLMASK 0xffffffffu

__device__ __forceinline__ float ftanh(float x) {
    float e = __expf(2.0f * x);
    return 1.0f - __fdividef(2.0f, e + 1.0f);
}
__device__ __forceinline__ float softplusf(float x) {
    return log1pf(__expf(x));
}

// One warp (32 threads) per batch element. Warp-synchronous UKF over T steps.
__global__ void __launch_bounds__(32) ukf_kernel(
    const float* __restrict__ X0, const float* __restrict__ u, const float* __restrict__ yy,
    const float* __restrict__ W1, const float* __restrict__ b1,
    const float* __restrict__ W2, const float* __restrict__ b2,
    const float* __restrict__ Hm, const float* __restrict__ lq,
    const float* __restrict__ lr, const float* __restrict__ lp0,
    float* __restrict__ outX, float* __restrict__ outP,
    float* __restrict__ outQ, float* __restrict__ outR,
    int T)
{
    const float JIT = 1e-4f;
    const int b = blockIdx.x;
    const int lane = threadIdx.x;

    __shared__ __align__(16) float sP[72];        // persistent P (8x9 padded)
    __shared__ __align__(16) float sA[72];        // chol workspace (L)
    __shared__ __align__(16) float sPp[72];       // P_pred
    __shared__ __align__(16) float sHid[17 * 36]; // tanh activations
    __shared__ __align__(16) float sDx[17 * 12];
    __shared__ float sDy[17 * 4];
    __shared__ float sx[8], sxp[8];
    __shared__ float sSy[20], sInvd[4], sPxy[32], sK[32], sU[32], sInno[4];

    const int o  = lane & 7;   // output/state index for this lane
    const int q  = lane >> 3;  // sigma-point group (0..3)
    const int m  = lane & 3;   // measurement index
    const int i1 = q;          // P_pred row (first of two)
    const int i2 = q + 4;      // P_pred row (second)
    const int j  = o;          // P_pred col
    const int pn = lane >> 2;  // Pxy row (0..7)
    const int si = pn & 3;     // Sy row for lanes<16

    // ---- persistent per-lane weights in registers ----
    float w1c[10];
    #pragma unroll
    for (int d = 0; d < 10; ++d) w1c[d] = W1[d * 32 + lane];
    float b1v = b1[lane];
    float w2c[32];
    #pragma unroll
    for (int h = 0; h < 32; ++h) w2c[h] = W2[h * 8 + o];
    float b2o = b2[o];
    float hmr[8];
    #pragma unroll
    for (int d = 0; d < 8; ++d) hmr[d] = Hm[m * 8 + d];

    float cD1 = (i1 == j) ? (softplusf(lq[i1]) + JIT) : 0.0f;
    float cD2 = (i2 == j) ? (softplusf(lq[i2]) + JIT) : 0.0f;
    float radd = (lane < 16 && si == m) ? softplusf(lr[si]) : 0.0f;

    // ---- t = 0 outputs + state init ----
    if (lane < 8) {
        float xv = X0[b * 8 + lane];
        sx[lane] = xv;
        outX[(long)b * T * 8 + lane] = xv;
    }
    #pragma unroll
    for (int rep = 0; rep < 2; ++rep) {
        int idx = lane + 32 * rep;
        int ii = idx >> 3, jj = idx & 7;
        float pv = (ii == jj) ? softplusf(lp0[ii]) : 0.0f;
        sP[ii * 9 + jj] = pv;
        outP[(long)b * T * 64 + idx] = pv;
    }
    if (lane == 0) { outQ[(long)b * T] = 0.0f; outR[(long)b * T] = 0.0f; }
    __syncwarp();

    for (int t = 1; t < T; ++t) {
        float u0 = u[((long)b * T + (t - 1)) * 2 + 0];
        float u1 = u[((long)b * T + (t - 1)) * 2 + 1];

        // ---- A = c*P + JIT*I  (c = n = 8; lam = 0) ----
        {
            int idx = lane; int ii = idx >> 3, jj = idx & 7;
            sA[ii * 9 + jj] = 8.0f * sP[ii * 9 + jj] + ((ii == jj) ? JIT : 0.0f);
            idx = lane + 32; ii = idx >> 3; jj = idx & 7;
            sA[ii * 9 + jj] = 8.0f * sP[ii * 9 + jj] + ((ii == jj) ? JIT : 0.0f);
        }
        // ---- cooperative 8x8 Cholesky: sA -> L (lower) ----
        #pragma unroll
        for (int k = 0; k < 8; ++k) {
            __syncwarp();
            float Akk = sA[k * 9 + k];
            float inv = rsqrtf(Akk);
            if (lane == k) sA[k * 9 + k] = Akk * inv;  // sqrt
            float v = 0.0f;
            if (lane > k && lane < 8) { v = sA[lane * 9 + k] * inv; sA[lane * 9 + k] = v; }
            __syncwarp();
            if (lane > k && lane < 8) {
                #pragma unroll
                for (int jj = k + 1; jj < 8; ++jj)
                    if (jj <= lane) sA[lane * 9 + jj] -= v * sA[jj * 9 + k];
            }
        }
        __syncwarp();

        // ---- L row for this lane's state index o, with explicit zeros above diag ----
        float Lrow[8];
        #pragma unroll
        for (int i = 0; i < 8; ++i)
            Lrow[i] = (i <= o) ? sA[o * 9 + i] : 0.0f;

        // ---- hidden layer, factored: hid[s] = tanh(base +/- G[i]) ----
        float base = b1v + u0 * w1c[8] + u1 * w1c[9];
        #pragma unroll
        for (int d = 0; d < 8; ++d) base += sx[d] * w1c[d];
        float G[8];
        #pragma unroll
        for (int i = 0; i < 8; ++i) {
            float g = 0.0f;
            #pragma unroll
            for (int d = i; d < 8; ++d) g += sA[d * 9 + i] * w1c[d];  // L[d][i]
            G[i] = g;
        }
        sHid[0 * 36 + lane] = ftanh(base);
        #pragma unroll
        for (int i = 0; i < 8; ++i) {
            sHid[(1 + i) * 36 + lane] = ftanh(base + G[i]);
            sHid[(9 + i) * 36 + lane] = ftanh(base - G[i]);
        }
        __syncwarp();

        // ---- output layer + x_pred + dx.  lane handles (s = 4g+q, o) ----
        float xo = sx[o];
        float pf[5];
        float xsum = 0.0f;
        #pragma unroll
        for (int g = 0; g < 5; ++g) {
            int s = 4 * g + q;
            bool valid = (s < 17);
            int ss = valid ? s : 0;
            const float4* hp = reinterpret_cast<const float4*>(&sHid[ss * 36]);
            float e = b2o;
            #pragma unroll
            for (int hh = 0; hh < 8; ++hh) {
                float4 hv = hp[hh];
                e += hv.x * w2c[4 * hh + 0] + hv.y * w2c[4 * hh + 1]
                   + hv.z * w2c[4 * hh + 2] + hv.w * w2c[4 * hh + 3];
            }
            float delta = 0.0f;
            if (ss >= 1 && ss <= 8) delta = Lrow[ss - 1];    // +L[o][i], zero above diag
            else if (ss >= 9)       delta = -Lrow[ss - 9];   // -L[o][i]
            float p = xo + delta + e;
            pf[g] = p;
            if (valid && s >= 1) xsum += p;   // Wm[0] = 0
        }
        xsum += __shfl_xor_sync(FULLMASK, xsum, 8);
        xsum += __shfl_xor_sync(FULLMASK, xsum, 16);
        float xpred = xsum * 0.0625f;
        if (q == 0) sxp[o] = xpred;
        #pragma unroll
        for (int g = 0; g < 5; ++g) {
            int s = 4 * g + q;
            if (s < 17) sDx[s * 12 + o] = pf[g] - xpred;
        }
        __syncwarp();

        // ---- dy = dx * Hm^T  (exact for linear h) ----
        {
            const int sb = lane >> 2;
            #pragma unroll
            for (int g2 = 0; g2 < 3; ++g2) {
                int s = sb + 8 * g2;
                bool valid = (s < 17);
                int ss = valid ? s : 0;
                const float4* dp = reinterpret_cast<const float4*>(&sDx[ss * 12]);
                float4 d0 = dp[0], d1 = dp[1];
                float dv = hmr[0] * d0.x + hmr[1] * d0.y + hmr[2] * d0.z + hmr[3] * d0.w
                         + hmr[4] * d1.x + hmr[5] * d1.y + hmr[6] * d1.z + hmr[7] * d1.w;
                if (valid) sDy[s * 4 + m] = dv;
            }
        }
        __syncwarp();

        // ---- Sy (4x4, lanes<16) and Pxy (8x4, all lanes) ----
        {
            float accP = 0.0f, accS = 0.0f;
            #pragma unroll 4
            for (int s = 0; s < 17; ++s) {
                float dxn = sDx[s * 12 + pn];
                float dym = sDy[s * 4 + m];
                float dyi = sDy[s * 4 + si];
                float wsc = (s == 0) ? 32.0f : 1.0f;   // Wc0=2 = 32/16
                accP += (dxn * wsc) * dym;
                accS += (dyi * wsc) * dym;
            }
            sPxy[pn * 4 + m] = accP * 0.0625f;
            if (lane < 16) sSy[si * 5 + m] = accS * 0.0625f + radd;
        }
        // ---- P_pred (2 entries per lane) ----
        {
            float a1 = 0.0f, a2 = 0.0f;
            #pragma unroll 4
            for (int s = 0; s < 17; ++s) {
                float dxj = sDx[s * 12 + j];
                if (s == 0) dxj *= 32.0f;
                a1 += sDx[s * 12 + i1] * dxj;
                a2 += sDx[s * 12 + i2] * dxj;
            }
            sPp[i1 * 9 + j] = a1 * 0.0625f + cD1;  // + Q diag + JIT
            sPp[i2 * 9 + j] = a2 * 0.0625f + cD2;
        }
        __syncwarp();

        // ---- 4x4 Cholesky of Sy (lanes 0..3) ----
        #pragma unroll
        for (int k = 0; k < 4; ++k) {
            __syncwarp();
            float Akk = sSy[k * 5 + k];
            float inv = rsqrtf(Akk);
            if (lane == k) { sSy[k * 5 + k] = Akk * inv; sInvd[k] = inv; }
            float v = 0.0f;
            if (lane > k && lane < 4) { v = sSy[lane * 5 + k] * inv; sSy[lane * 5 + k] = v; }
            __syncwarp();
            if (lane > k && lane < 4) {
                #pragma unroll
                for (int jj = k + 1; jj < 4; ++jj)
                    if (jj <= lane) sSy[lane * 5 + jj] -= v * sSy[jj * 5 + k];
            }
        }
        __syncwarp();
        if (lane == 0) {
            float r_e = __logf(sSy[0]) + __logf(sSy[6]) + __logf(sSy[12]) + __logf(sSy[18]);
            outR[(long)b * T + t] = r_e;   // 0.5*logdet = sum log diag(L)
        }
        // ---- K = Pxy * Sy^{-1} via two triangular solves (lanes 0..7) ----
        if (lane < 8) {
            float L10 = sSy[5],  L20 = sSy[10], L21 = sSy[11];
            float L30 = sSy[15], L31 = sSy[16], L32 = sSy[17];
            float d0 = sInvd[0], d1 = sInvd[1], d2 = sInvd[2], d3 = sInvd[3];
            float w0 = sPxy[lane * 4 + 0], w1 = sPxy[lane * 4 + 1];
            float w2 = sPxy[lane * 4 + 2], w3 = sPxy[lane * 4 + 3];
            w0 = w0 * d0;
            w1 = (w1 - L10 * w0) * d1;
            w2 = (w2 - L20 * w0 - L21 * w1) * d2;
            w3 = (w3 - L30 * w0 - L31 * w1 - L32 * w2) * d3;
            float z3 = w3 * d3;
            float z2 = (w2 - L32 * z3) * d2;
            float z1 = (w1 - L21 * z2 - L31 * z3) * d1;
            float z0 = (w0 - L10 * z1 - L20 * z2 - L30 * z3) * d0;
            sK[lane * 4 + 0] = z0; sK[lane * 4 + 1] = z1;
            sK[lane * 4 + 2] = z2; sK[lane * 4 + 3] = z3;
        }
        // ---- innovation (lanes 0..3): y_t - Hm*x_pred ----
        if (lane < 4) {
            float yp = 0.0f;
            #pragma unroll
            for (int d = 0; d < 8; ++d) yp += hmr[d] * sxp[d];
            sInno[lane] = yy[((long)b * T + t) * 4 + lane] - yp;
        }
        __syncwarp();
        // ---- x_new (lanes 0..7) and U = K * Ls (all lanes) ----
        if (lane < 8) {
            float xn = sxp[lane];
            #pragma unroll
            for (int mm = 0; mm < 4; ++mm) xn += sK[lane * 4 + mm] * sInno[mm];
            sx[lane] = xn;
            outX[((long)b * T + t) * 8 + lane] = xn;
        }
        {
            float uacc = 0.0f;
            #pragma unroll
            for (int jj = 0; jj < 4; ++jj)
                if (jj >= m) uacc += sK[pn * 4 + jj] * sSy[jj * 5 + m];
            sU[pn * 4 + m] = uacc;
        }
        __syncwarp();
        // ---- P_new = P_pred - U U^T + JIT*I  (bitwise symmetric) ----
        {
            float Uj0 = sU[j * 4 + 0], Uj1 = sU[j * 4 + 1], Uj2 = sU[j * 4 + 2], Uj3 = sU[j * 4 + 3];
            float Ua0 = sU[i1 * 4 + 0], Ua1 = sU[i1 * 4 + 1], Ua2 = sU[i1 * 4 + 2], Ua3 = sU[i1 * 4 + 3];
            float Ub0 = sU[i2 * 4 + 0], Ub1 = sU[i2 * 4 + 1], Ub2 = sU[i2 * 4 + 2], Ub3 = sU[i2 * 4 + 3];
            float p1 = sPp[i1 * 9 + j] - (Ua0 * Uj0 + Ua1 * Uj1 + Ua2 * Uj2 + Ua3 * Uj3)
                     + ((i1 == j) ? JIT : 0.0f);
            float p2 = sPp[i2 * 9 + j] - (Ub0 * Uj0 + Ub1 * Uj1 + Ub2 * Uj2 + Ub3 * Uj3)
                     + ((i2 == j) ? JIT : 0.0f);
            sP[i1 * 9 + j] = p1; sP[i2 * 9 + j] = p2;
            long bp = ((long)b * T + t) * 64;
            outP[bp + i1 * 8 + j] = p1;
            outP[bp + i2 * 8 + j] = p2;
        }
        __syncwarp();
        // ---- q_e = 0.5*logdet(P_pred): Cholesky sPp in place ----
        #pragma unroll
        for (int k = 0; k < 8; ++k) {
            __syncwarp();
            float Akk = sPp[k * 9 + k];
            float inv = rsqrtf(Akk);
            if (lane == k) sPp[k * 9 + k] = Akk * inv;
            float v = 0.0f;
            if (lane > k && lane < 8) { v = sPp[lane * 9 + k] * inv; sPp[lane * 9 + k] = v; }
            __syncwarp();
            if (lane > k && lane < 8) {
                #pragma unroll
                for (int jj = k + 1; jj < 8; ++jj)
                    if (jj <= lane) sPp[lane * 9 + jj] -= v * sPp[jj * 9 + k];
            }
        }
        __syncwarp();
        {
            float lg = (lane < 8) ? __logf(sPp[lane * 9 + lane]) : 0.0f;
            lg += __shfl_xor_sync(FULLMASK, lg, 1);
            lg += __shfl_xor_sync(FULLMASK, lg, 2);
            lg += __shfl_xor_sync(FULLMASK, lg, 4);
            if (lane == 0) outQ[(long)b * T + t] = lg;
        }
        __syncwarp();
    }
}

extern "C" void kernel_launch(void* const* d_in, const int* in_sizes, int n_in,
                              void* d_out, int out_size) {
    const float* X0  = (const float*)d_in[0];
    const float* u   = (const float*)d_in[1];
    const float* yv  = (const float*)d_in[2];
    const float* W1  = (const float*)d_in[3];
    const float* b1  = (const float*)d_in[4];
    const float* W2  = (const float*)d_in[5];
    const float* b2  = (const float*)d_in[6];
    const float* Hm  = (const float*)d_in[7];
    const float* lq  = (const float*)d_in[8];
    const float* lr  = (const float*)d_in[9];
    const float* lp0 = (const float*)d_in[10];

    const int B = in_sizes[0] / 8;                 // 1024
    const int T = in_sizes[1] / (B * 2);           // 256

    float* out  = (float*)d_out;
    float* outX = out;
    float* outP = out + (long)B * T * 8;
    float* outQ = out + (long)B * T * (8 + 64);
    float* outR = outQ + (long)B * T;

    ukf_kernel<<<B, 32>>>(X0, u, yv, W1, b1, W2, b2, Hm, lq, lr, lp0,
                          outX, outP, outQ, outR, T);
}

// round 3
// speedup vs baseline: 2.3023x; 2.3023x over previous
#include <cuda_runtime.h>

#define FULLMASK 0xffffffffu

__device__ __forceinline__ float ftanh(float x) {
    float e = __expf(2.0f * x);
    return 1.0f - __fdividef(2.0f, e + 1.0f);
}
__device__ __forceinline__ float softplusf(float x) {
    return log1pf(__expf(x));
}

// One warp per batch element. Shuffle-heavy warp-synchronous UKF.
__global__ void __launch_bounds__(32) ukf_kernel(
    const float* __restrict__ X0, const float* __restrict__ u, const float* __restrict__ yy,
    const float* __restrict__ W1, const float* __restrict__ b1,
    const float* __restrict__ W2, const float* __restrict__ b2,
    const float* __restrict__ Hm, const float* __restrict__ lq,
    const float* __restrict__ lr, const float* __restrict__ lp0,
    float* __restrict__ outX, float* __restrict__ outP,
    float* __restrict__ outQ, float* __restrict__ outR,
    int T)
{
    const float JIT = 1e-4f;
    const int b = blockIdx.x;
    const int lane = threadIdx.x;

    __shared__ float sP[72];                       // P_new handoff (8x9)
    __shared__ float sPp[72];                      // P_pred handoff (8x9)
    __shared__ __align__(16) float sHid[17 * 36];  // tanh activations
    __shared__ __align__(16) float sDx[17 * 12];
    __shared__ float sDy[17 * 4];

    const int o  = lane & 7;    // state index / chol row
    const int q  = lane >> 3;   // sigma group / P row base
    const int m  = lane & 3;    // measurement index
    const int pn = lane >> 2;   // Pxy row
    const int si = pn & 3;      // Sy row (lanes 0-15 canonical)
    const int i1 = q, i2 = q + 4;
    const int g8 = lane & 8;    // dual-chol shuffle base
    const int b4 = lane & 28;   // 4-group base
    const int r4 = lane & 3;    // Sy chol row

    // ---- persistent per-lane weights in registers ----
    float w1c[10];
    #pragma unroll
    for (int d = 0; d < 10; ++d) w1c[d] = W1[d * 32 + lane];
    float b1v = b1[lane];
    float w2c[32];
    #pragma unroll
    for (int h = 0; h < 32; ++h) w2c[h] = W2[h * 8 + o];
    float b2o = b2[o];
    float hmr[8];
    #pragma unroll
    for (int d = 0; d < 8; ++d) hmr[d] = Hm[m * 8 + d];

    const float cD1 = (i1 == o) ? (softplusf(lq[i1]) + JIT) : 0.0f;
    const float cD2 = (i2 == o) ? (softplusf(lq[i2]) + JIT) : 0.0f;
    const float radd = (si == m) ? softplusf(lr[si]) : 0.0f;

    // ---- init: t=0 outputs, P0, identity Pp (benign for t=1 dual-chol) ----
    float xreg = X0[b * 8 + o];
    if (lane < 8) outX[(long)b * T * 8 + lane] = xreg;
    #pragma unroll
    for (int rep = 0; rep < 2; ++rep) {
        int idx = lane + 32 * rep;
        int ii = idx >> 3, jj = idx & 7;
        float pv = (ii == jj) ? softplusf(lp0[ii]) : 0.0f;
        sP[ii * 9 + jj] = pv;
        sPp[ii * 9 + jj] = (ii == jj) ? 1.0f : 0.0f;
        outP[(long)b * T * 64 + idx] = pv;
    }
    if (lane == 0) { outQ[(long)b * T] = 0.0f; outR[(long)b * T] = 0.0f; }
    __syncwarp();

    for (int t = 1; t < T; ++t) {
        const float u0 = u[((long)b * T + (t - 1)) * 2 + 0];
        const float u1 = u[((long)b * T + (t - 1)) * 2 + 1];

        // ==== dual shuffle-Cholesky: bit3=0 lanes -> A=8P+JIT*I ; bit3=1 -> Pp_prev ====
        float a[8];
        #pragma unroll
        for (int c = 0; c < 8; ++c)
            a[c] = g8 ? sPp[o * 9 + c]
                      : (8.0f * sP[o * 9 + c] + ((o == c) ? JIT : 0.0f));
        float mydiag8 = 1.0f;
        #pragma unroll
        for (int k = 0; k < 8; ++k) {
            float akk = __shfl_sync(FULLMASK, a[k], g8 + k);
            float inv = rsqrtf(akk);
            float lk = a[k] * inv;
            if (o == k) { a[k] = akk * inv; mydiag8 = a[k]; }
            else if (o > k) a[k] = lk;
            #pragma unroll
            for (int jj = k + 1; jj < 8; ++jj) {
                float lj = __shfl_sync(FULLMASK, a[k], g8 + jj);
                if (o >= jj) a[jj] -= a[k] * lj;
            }
        }
        // deferred q_e of previous step (lanes 8-15 hold L(Pp_prev))
        {
            float lg = __logf(mydiag8);
            lg += __shfl_xor_sync(FULLMASK, lg, 1);
            lg += __shfl_xor_sync(FULLMASK, lg, 2);
            lg += __shfl_xor_sync(FULLMASK, lg, 4);
            if (lane == 8 && t >= 2) outQ[(long)b * T + (t - 1)] = lg;
        }
        // L(A) row for own state o (src lanes 0..7 hold L(A) rows)
        float Lrow[8];
        #pragma unroll
        for (int i = 0; i < 8; ++i) {
            float lv = __shfl_sync(FULLMASK, a[i], o);
            Lrow[i] = (i <= o) ? lv : 0.0f;
        }
        // G[i] = sum_{d>=i} L[d][i] * w1c[d]
        float G[8];
        #pragma unroll
        for (int i = 0; i < 8; ++i) {
            float g = 0.0f;
            #pragma unroll
            for (int d = i; d < 8; ++d)
                g += __shfl_sync(FULLMASK, a[i], d) * w1c[d];
            G[i] = g;
        }
        // hidden-layer base from register state x
        float bx = b1v + u0 * w1c[8] + u1 * w1c[9];
        #pragma unroll
        for (int d = 0; d < 8; ++d)
            bx += __shfl_sync(FULLMASK, xreg, d) * w1c[d];

        sHid[0 * 36 + lane] = ftanh(bx);
        #pragma unroll
        for (int i = 0; i < 8; ++i) {
            sHid[(1 + i) * 36 + lane] = ftanh(bx + G[i]);
            sHid[(9 + i) * 36 + lane] = ftanh(bx - G[i]);
        }
        __syncwarp();

        // ==== output layer + x_pred + dx ====
        float pf[5];
        float xsum = 0.0f;
        #pragma unroll
        for (int g = 0; g < 5; ++g) {
            int s = 4 * g + q;
            bool valid = (s < 17);
            int ss = valid ? s : 0;
            const float4* hp = reinterpret_cast<const float4*>(&sHid[ss * 36]);
            float e = b2o;
            #pragma unroll
            for (int hh = 0; hh < 8; ++hh) {
                float4 hv = hp[hh];
                e += hv.x * w2c[4 * hh] + hv.y * w2c[4 * hh + 1]
                   + hv.z * w2c[4 * hh + 2] + hv.w * w2c[4 * hh + 3];
            }
            float delta = 0.0f;
            if (ss >= 1 && ss <= 8) delta = Lrow[ss - 1];
            else if (ss >= 9)       delta = -Lrow[ss - 9];
            float p = xreg + delta + e;
            pf[g] = p;
            if (valid && s >= 1) xsum += p;      // Wm[0] = 0
        }
        xsum += __shfl_xor_sync(FULLMASK, xsum, 8);
        xsum += __shfl_xor_sync(FULLMASK, xsum, 16);
        const float xpred = xsum * 0.0625f;
        #pragma unroll
        for (int g = 0; g < 5; ++g) {
            int s = 4 * g + q;
            if (s < 17) sDx[s * 12 + o] = pf[g] - xpred;
        }
        __syncwarp();

        // ==== dy = dx * Hm^T ====
        {
            const int sb = lane >> 2;
            #pragma unroll
            for (int g2 = 0; g2 < 3; ++g2) {
                int s = sb + 8 * g2;
                bool valid = (s < 17);
                int ss = valid ? s : 0;
                const float4* dp = reinterpret_cast<const float4*>(&sDx[ss * 12]);
                float4 d0 = dp[0], d1 = dp[1];
                float dv = hmr[0] * d0.x + hmr[1] * d0.y + hmr[2] * d0.z + hmr[3] * d0.w
                         + hmr[4] * d1.x + hmr[5] * d1.y + hmr[6] * d1.z + hmr[7] * d1.w;
                if (valid) sDy[s * 4 + m] = dv;
            }
        }
        __syncwarp();

        // ==== merged moments: Pxy(pn,m), Sy(si,m), Ppred(i1,o),(i2,o) ====
        float accP, accS, a1, a2;
        {
            float dxi1 = sDx[i1], dxi2 = sDx[i2], dxj = sDx[o], dxp = sDx[pn];
            float dym = sDy[m], dyi = sDy[si];
            accP = 32.0f * dxp * dym;   // Wc0 = 2 = 32/16
            accS = 32.0f * dyi * dym;
            a1 = 32.0f * dxi1 * dxj;
            a2 = 32.0f * dxi2 * dxj;
            #pragma unroll
            for (int s = 1; s < 17; ++s) {
                dxi1 = sDx[s * 12 + i1]; dxi2 = sDx[s * 12 + i2];
                dxj = sDx[s * 12 + o];   dxp = sDx[s * 12 + pn];
                dym = sDy[s * 4 + m];    dyi = sDy[s * 4 + si];
                accP += dxp * dym;
                accS += dyi * dym;
                a1 += dxi1 * dxj;
                a2 += dxi2 * dxj;
            }
        }
        accP *= 0.0625f;
        accS = accS * 0.0625f + radd;
        const float ppa = a1 * 0.0625f + cD1;
        const float ppb = a2 * 0.0625f + cD2;
        sPp[i1 * 9 + o] = ppa;   // handoff for next-iter deferred chol
        sPp[i2 * 9 + o] = ppb;

        // ==== Sy 4x4 shuffle-Cholesky (4-lane groups, rows fetched by shuffle) ====
        float s4[4];
        #pragma unroll
        for (int c = 0; c < 4; ++c)
            s4[c] = __shfl_sync(FULLMASK, accS, r4 * 4 + c);
        float myinv4 = 1.0f, mydiag4 = 1.0f;
        #pragma unroll
        for (int k = 0; k < 4; ++k) {
            float akk = __shfl_sync(FULLMASK, s4[k], b4 + k);
            float inv = rsqrtf(akk);
            float lk = s4[k] * inv;
            if (r4 == k) { s4[k] = akk * inv; myinv4 = inv; mydiag4 = s4[k]; }
            else if (r4 > k) s4[k] = lk;
            #pragma unroll
            for (int jj = k + 1; jj < 4; ++jj) {
                float lj = __shfl_sync(FULLMASK, s4[k], b4 + jj);
                if (r4 >= jj) s4[jj] -= s4[k] * lj;
            }
        }
        {
            float lg = __logf(mydiag4);
            lg += __shfl_xor_sync(FULLMASK, lg, 1);
            lg += __shfl_xor_sync(FULLMASK, lg, 2);
            if (lane == 0) outR[(long)b * T + t] = lg;
        }
        // broadcast L(Sy) pieces
        const float d0 = __shfl_sync(FULLMASK, myinv4, b4 + 0);
        const float d1 = __shfl_sync(FULLMASK, myinv4, b4 + 1);
        const float d2 = __shfl_sync(FULLMASK, myinv4, b4 + 2);
        const float d3 = __shfl_sync(FULLMASK, myinv4, b4 + 3);
        const float Ld0 = __shfl_sync(FULLMASK, mydiag4, b4 + 0);
        const float Ld1 = __shfl_sync(FULLMASK, mydiag4, b4 + 1);
        const float Ld2 = __shfl_sync(FULLMASK, mydiag4, b4 + 2);
        const float Ld3 = __shfl_sync(FULLMASK, mydiag4, b4 + 3);
        const float L10 = __shfl_sync(FULLMASK, s4[0], b4 + 1);
        const float L20 = __shfl_sync(FULLMASK, s4[0], b4 + 2);
        const float L30 = __shfl_sync(FULLMASK, s4[0], b4 + 3);
        const float L21 = __shfl_sync(FULLMASK, s4[1], b4 + 2);
        const float L31 = __shfl_sync(FULLMASK, s4[1], b4 + 3);
        const float L32 = __shfl_sync(FULLMASK, s4[2], b4 + 3);

        // ==== K row o via two triangular solves (all lanes, Pxy row via shuffle) ====
        float w0 = __shfl_sync(FULLMASK, accP, o * 4 + 0);
        float w1 = __shfl_sync(FULLMASK, accP, o * 4 + 1);
        float w2 = __shfl_sync(FULLMASK, accP, o * 4 + 2);
        float w3 = __shfl_sync(FULLMASK, accP, o * 4 + 3);
        w0 = w0 * d0;
        w1 = (w1 - L10 * w0) * d1;
        w2 = (w2 - L20 * w0 - L21 * w1) * d2;
        w3 = (w3 - L30 * w0 - L31 * w1 - L32 * w2) * d3;
        float z3 = w3 * d3;
        float z2 = (w2 - L32 * z3) * d2;
        float z1 = (w1 - L21 * z2 - L31 * z3) * d1;
        float z0 = (w0 - L10 * z1 - L20 * z2 - L30 * z3) * d0;

        // ==== innovation & state update ====
        float ypm = 0.0f;
        #pragma unroll
        for (int d = 0; d < 8; ++d)
            ypm += hmr[d] * __shfl_sync(FULLMASK, xpred, d);
        float inno = yy[((long)b * T + t) * 4 + m] - ypm;
        const float in0 = __shfl_sync(FULLMASK, inno, b4 + 0);
        const float in1 = __shfl_sync(FULLMASK, inno, b4 + 1);
        const float in2 = __shfl_sync(FULLMASK, inno, b4 + 2);
        const float in3 = __shfl_sync(FULLMASK, inno, b4 + 3);
        float xn = xpred + z0 * in0 + z1 * in1 + z2 * in2 + z3 * in3;
        xreg = xn;
        if (lane < 8) outX[((long)b * T + t) * 8 + o] = xn;

        // ==== U = K * L(Sy), P_new = Ppred - U U^T + JIT*I (bitwise symmetric) ====
        float U0 = z0 * Ld0 + z1 * L10 + z2 * L20 + z3 * L30;
        float U1 = z1 * Ld1 + z2 * L21 + z3 * L31;
        float U2 = z2 * Ld2 + z3 * L32;
        float U3 = z3 * Ld3;
        float Ua0 = __shfl_sync(FULLMASK, U0, q);
        float Ua1 = __shfl_sync(FULLMASK, U1, q);
        float Ua2 = __shfl_sync(FULLMASK, U2, q);
        float Ua3 = __shfl_sync(FULLMASK, U3, q);
        float Ub0 = __shfl_sync(FULLMASK, U0, q + 4);
        float Ub1 = __shfl_sync(FULLMASK, U1, q + 4);
        float Ub2 = __shfl_sync(FULLMASK, U2, q + 4);
        float Ub3 = __shfl_sync(FULLMASK, U3, q + 4);
        float p1 = ppa - (Ua0 * U0 + Ua1 * U1 + Ua2 * U2 + Ua3 * U3) + ((i1 == o) ? JIT : 0.0f);
        float p2 = ppb - (Ub0 * U0 + Ub1 * U1 + Ub2 * U2 + Ub3 * U3) + ((i2 == o) ? JIT : 0.0f);
        sP[i1 * 9 + o] = p1;
        sP[i2 * 9 + o] = p2;
        long bp = ((long)b * T + t) * 64;
        outP[bp + i1 * 8 + o] = p1;
        outP[bp + i2 * 8 + o] = p2;
        __syncwarp();
    }

    // ==== epilogue: q_e[T-1] from final P_pred ====
    {
        float a[8];
        #pragma unroll
        for (int c = 0; c < 8; ++c) a[c] = sPp[o * 9 + c];
        float md = 1.0f;
        #pragma unroll
        for (int k = 0; k < 8; ++k) {
            float akk = __shfl_sync(FULLMASK, a[k], k);
            float inv = rsqrtf(akk);
            float lk = a[k] * inv;
            if (o == k) { a[k] = akk * inv; md = a[k]; }
            else if (o > k) a[k] = lk;
            #pragma unroll
            for (int jj = k + 1; jj < 8; ++jj) {
                float lj = __shfl_sync(FULLMASK, a[k], jj);
                if (o >= jj) a[jj] -= a[k] * lj;
            }
        }
        float lg = __logf(md);
        lg += __shfl_xor_sync(FULLMASK, lg, 1);
        lg += __shfl_xor_sync(FULLMASK, lg, 2);
        lg += __shfl_xor_sync(FULLMASK, lg, 4);
        if (lane == 0) outQ[(long)b * T + (T - 1)] = lg;
    }
}

extern "C" void kernel_launch(void* const* d_in, const int* in_sizes, int n_in,
                              void* d_out, int out_size) {
    const float* X0  = (const float*)d_in[0];
    const float* u   = (const float*)d_in[1];
    const float* yv  = (const float*)d_in[2];
    const float* W1  = (const float*)d_in[3];
    const float* b1  = (const float*)d_in[4];
    const float* W2  = (const float*)d_in[5];
    const float* b2  = (const float*)d_in[6];
    const float* Hm  = (const float*)d_in[7];
    const float* lq  = (const float*)d_in[8];
    const float* lr  = (const float*)d_in[9];
    const float* lp0 = (const float*)d_in[10];

    const int B = in_sizes[0] / 8;                 // 1024
    const int T = in_sizes[1] / (B * 2);           // 256

    float* out  = (float*)d_out;
    float* outX = out;
    float* outP = out + (long)B * T * 8;
    float* outQ = out + (long)B * T * (8 + 64);
    float* outR = outQ + (long)B * T;

    ukf_kernel<<<B, 32>>>(X0, u, yv, W1, b1, W2, b2, Hm, lq, lr, lp0,
                          outX, outP, outQ, outR, T);
}

// round 4
// speedup vs baseline: 2.4084x; 1.0461x over previous
#include <cuda_runtime.h>

#define FULLMASK 0xffffffffu

__device__ __forceinline__ float ftanh(float x) {
    float e = __expf(2.0f * x);
    return 1.0f - __fdividef(2.0f, e + 1.0f);
}
__device__ __forceinline__ float softplusf(float x) {
    return log1pf(__expf(x));
}

// One warp per batch element. Shuffle-heavy warp-synchronous UKF.
__global__ void __launch_bounds__(32) ukf_kernel(
    const float* __restrict__ X0, const float* __restrict__ u, const float* __restrict__ yy,
    const float* __restrict__ W1, const float* __restrict__ b1,
    const float* __restrict__ W2, const float* __restrict__ b2,
    const float* __restrict__ Hm, const float* __restrict__ lq,
    const float* __restrict__ lr, const float* __restrict__ lp0,
    float* __restrict__ outX, float* __restrict__ outP,
    float* __restrict__ outQ, float* __restrict__ outR,
    int T)
{
    const float JIT = 1e-4f;
    const int b = blockIdx.x;
    const int lane = threadIdx.x;

    __shared__ float sP[72];                       // P_new handoff (8x9)
    __shared__ float sPp[72];                      // P_pred handoff (8x9)
    __shared__ __align__(16) float sHid[17 * 36];  // tanh activations
    __shared__ __align__(16) float sDxT[8 * 20];   // dx TRANSPOSED: [col][s], 80B rows

    const int o  = lane & 7;    // state index / chol row
    const int q  = lane >> 3;   // sigma group / P row base
    const int m  = lane & 3;    // measurement index
    const int pn = lane >> 2;   // Pxy row
    const int si = pn & 3;      // Sy row index for this lane
    const int i1 = q, i2 = q + 4;
    const int g8 = lane & 8;    // dual-chol shuffle base
    const int b4 = lane & 28;   // 4-group base
    const int r4 = lane & 3;    // Sy chol row

    // ---- persistent per-lane weights in registers ----
    float w1c[10];
    #pragma unroll
    for (int d = 0; d < 10; ++d) w1c[d] = W1[d * 32 + lane];
    float b1v = b1[lane];
    float w2c[32];
    #pragma unroll
    for (int h = 0; h < 32; ++h) w2c[h] = W2[h * 8 + o];
    float b2o = b2[o];
    float hmr[8];                 // Hm row m (this lane's measurement idx)
    #pragma unroll
    for (int d = 0; d < 8; ++d) hmr[d] = Hm[m * 8 + d];
    float hsr[8];                 // Hm row si (for Sy assembly)
    #pragma unroll
    for (int d = 0; d < 8; ++d) hsr[d] = Hm[si * 8 + d];

    const float cD1 = (i1 == o) ? (softplusf(lq[i1]) + JIT) : 0.0f;
    const float cD2 = (i2 == o) ? (softplusf(lq[i2]) + JIT) : 0.0f;
    const float radd = (si == m) ? softplusf(lr[si]) : 0.0f;

    // ---- init: t=0 outputs, P0, identity Pp (benign for t=1 dual-chol) ----
    float xreg = X0[b * 8 + o];
    if (lane < 8) outX[(long)b * T * 8 + lane] = xreg;
    #pragma unroll
    for (int rep = 0; rep < 2; ++rep) {
        int idx = lane + 32 * rep;
        int ii = idx >> 3, jj = idx & 7;
        float pv = (ii == jj) ? softplusf(lp0[ii]) : 0.0f;
        sP[ii * 9 + jj] = pv;
        sPp[ii * 9 + jj] = (ii == jj) ? 1.0f : 0.0f;
        outP[(long)b * T * 64 + idx] = pv;
    }
    if (lane == 0) { outQ[(long)b * T] = 0.0f; outR[(long)b * T] = 0.0f; }
    __syncwarp();

    for (int t = 1; t < T; ++t) {
        const float u0 = u[((long)b * T + (t - 1)) * 2 + 0];
        const float u1 = u[((long)b * T + (t - 1)) * 2 + 1];

        // ==== dual shuffle-Cholesky: bit3=0 lanes -> A=8P+JIT*I ; bit3=1 -> Pp_prev ====
        float a[8];
        #pragma unroll
        for (int c = 0; c < 8; ++c)
            a[c] = g8 ? sPp[o * 9 + c]
                      : (8.0f * sP[o * 9 + c] + ((o == c) ? JIT : 0.0f));
        float mydiag8 = 1.0f;
        #pragma unroll
        for (int k = 0; k < 8; ++k) {
            float akk = __shfl_sync(FULLMASK, a[k], g8 + k);
            float inv = rsqrtf(akk);
            float lk = a[k] * inv;
            if (o == k) { a[k] = akk * inv; mydiag8 = a[k]; }
            else if (o > k) a[k] = lk;
            #pragma unroll
            for (int jj = k + 1; jj < 8; ++jj) {
                float lj = __shfl_sync(FULLMASK, a[k], g8 + jj);
                if (o >= jj) a[jj] -= a[k] * lj;
            }
        }
        // deferred q_e of previous step (lanes 8-15 hold L(Pp_prev))
        {
            float lg = __logf(mydiag8);
            lg += __shfl_xor_sync(FULLMASK, lg, 1);
            lg += __shfl_xor_sync(FULLMASK, lg, 2);
            lg += __shfl_xor_sync(FULLMASK, lg, 4);
            if (lane == 8 && t >= 2) outQ[(long)b * T + (t - 1)] = lg;
        }
        // L(A) row for own state o (src lanes 0..7 hold L(A) rows)
        float Lrow[8];
        #pragma unroll
        for (int i = 0; i < 8; ++i) {
            float lv = __shfl_sync(FULLMASK, a[i], o);
            Lrow[i] = (i <= o) ? lv : 0.0f;
        }
        // G[i] = sum_{d>=i} L[d][i] * w1c[d]
        float G[8];
        #pragma unroll
        for (int i = 0; i < 8; ++i) {
            float g = 0.0f;
            #pragma unroll
            for (int d = i; d < 8; ++d)
                g += __shfl_sync(FULLMASK, a[i], d) * w1c[d];
            G[i] = g;
        }
        // hidden-layer base from register state x
        float bx = b1v + u0 * w1c[8] + u1 * w1c[9];
        #pragma unroll
        for (int d = 0; d < 8; ++d)
            bx += __shfl_sync(FULLMASK, xreg, d) * w1c[d];

        sHid[0 * 36 + lane] = ftanh(bx);
        #pragma unroll
        for (int i = 0; i < 8; ++i) {
            sHid[(1 + i) * 36 + lane] = ftanh(bx + G[i]);
            sHid[(9 + i) * 36 + lane] = ftanh(bx - G[i]);
        }
        __syncwarp();

        // ==== output layer + x_pred + dx (stored transposed) ====
        float pf[5];
        float xsum = 0.0f;
        #pragma unroll
        for (int g = 0; g < 5; ++g) {
            int s = 4 * g + q;
            bool valid = (s < 17);
            int ss = valid ? s : 0;
            const float4* hp = reinterpret_cast<const float4*>(&sHid[ss * 36]);
            float e = b2o;
            #pragma unroll
            for (int hh = 0; hh < 8; ++hh) {
                float4 hv = hp[hh];
                e += hv.x * w2c[4 * hh] + hv.y * w2c[4 * hh + 1]
                   + hv.z * w2c[4 * hh + 2] + hv.w * w2c[4 * hh + 3];
            }
            float delta = 0.0f;
            if (ss >= 1 && ss <= 8) delta = Lrow[ss - 1];
            else if (ss >= 9)       delta = -Lrow[ss - 9];
            float p = xreg + delta + e;
            pf[g] = p;
            if (valid && s >= 1) xsum += p;      // Wm[0] = 0
        }
        xsum += __shfl_xor_sync(FULLMASK, xsum, 8);
        xsum += __shfl_xor_sync(FULLMASK, xsum, 16);
        const float xpred = xsum * 0.0625f;
        #pragma unroll
        for (int g = 0; g < 5; ++g) {
            int s = 4 * g + q;
            if (s < 17) sDxT[o * 20 + s] = pf[g] - xpred;   // transposed, conflict-free
        }
        __syncwarp();

        // ==== Cx raw (16x scaled): a1 = 16*Cx[i1][o], a2 = 16*Cx[i2][o] ====
        float a1, a2;
        {
            const float4* cq = reinterpret_cast<const float4*>(&sDxT[i1 * 20]);
            const float4* c2 = reinterpret_cast<const float4*>(&sDxT[i2 * 20]);
            const float4* co = reinterpret_cast<const float4*>(&sDxT[o * 20]);
            float4 xq = cq[0], x2 = c2[0], xo = co[0];
            // s=0 carries Wc0 = 2 = 32/16
            a1 = 32.0f * xq.x * xo.x + xq.y * xo.y + xq.z * xo.z + xq.w * xo.w;
            a2 = 32.0f * x2.x * xo.x + x2.y * xo.y + x2.z * xo.z + x2.w * xo.w;
            #pragma unroll
            for (int c = 1; c < 4; ++c) {
                xq = cq[c]; x2 = c2[c]; xo = co[c];
                a1 += xq.x * xo.x + xq.y * xo.y + xq.z * xo.z + xq.w * xo.w;
                a2 += x2.x * xo.x + x2.y * xo.y + x2.z * xo.z + x2.w * xo.w;
            }
            float q16 = sDxT[i1 * 20 + 16], t16 = sDxT[i2 * 20 + 16], o16 = sDxT[o * 20 + 16];
            a1 += q16 * o16;
            a2 += t16 * o16;
        }
        const float ppa = a1 * 0.0625f + cD1;   // P_pred[i1][o]
        const float ppb = a2 * 0.0625f + cD2;   // P_pred[i2][o]
        sPp[i1 * 9 + o] = ppa;   // handoff for next-iter deferred chol
        sPp[i2 * 9 + o] = ppb;

        // ==== Pxy[pn][m] = (Cx Hm^T)[pn][m] via shuffled Cx entries ====
        float pxy = 0.0f;
        {
            const int sb8 = (pn & 3) * 8;
            #pragma unroll
            for (int d = 0; d < 8; ++d) {
                float v1 = __shfl_sync(FULLMASK, a1, sb8 + d);
                float v2 = __shfl_sync(FULLMASK, a2, sb8 + d);
                float cv = (pn < 4) ? v1 : v2;
                pxy += cv * hmr[d];
            }
            pxy *= 0.0625f;
        }
        // ==== Sy[si][m] = (Hm Pxy)[si][m] + R ====
        float syv = radd;
        #pragma unroll
        for (int d = 0; d < 8; ++d) {
            float pv = __shfl_sync(FULLMASK, pxy, d * 4 + m);
            syv += hsr[d] * pv;
        }

        // ==== Sy 4x4 shuffle-Cholesky (4-lane groups) ====
        float s4[4];
        #pragma unroll
        for (int c = 0; c < 4; ++c)
            s4[c] = __shfl_sync(FULLMASK, syv, r4 * 4 + c);
        float myinv4 = 1.0f, mydiag4 = 1.0f;
        #pragma unroll
        for (int k = 0; k < 4; ++k) {
            float akk = __shfl_sync(FULLMASK, s4[k], b4 + k);
            float inv = rsqrtf(akk);
            float lk = s4[k] * inv;
            if (r4 == k) { s4[k] = akk * inv; myinv4 = inv; mydiag4 = s4[k]; }
            else if (r4 > k) s4[k] = lk;
            #pragma unroll
            for (int jj = k + 1; jj < 4; ++jj) {
                float lj = __shfl_sync(FULLMASK, s4[k], b4 + jj);
                if (r4 >= jj) s4[jj] -= s4[k] * lj;
            }
        }
        {
            float lg = __logf(mydiag4);
            lg += __shfl_xor_sync(FULLMASK, lg, 1);
            lg += __shfl_xor_sync(FULLMASK, lg, 2);
            if (lane == 0) outR[(long)b * T + t] = lg;
        }
        // broadcast L(Sy) pieces
        const float d0 = __shfl_sync(FULLMASK, myinv4, b4 + 0);
        const float d1 = __shfl_sync(FULLMASK, myinv4, b4 + 1);
        const float d2 = __shfl_sync(FULLMASK, myinv4, b4 + 2);
        const float d3 = __shfl_sync(FULLMASK, myinv4, b4 + 3);
        const float Ld0 = __shfl_sync(FULLMASK, mydiag4, b4 + 0);
        const float Ld1 = __shfl_sync(FULLMASK, mydiag4, b4 + 1);
        const float Ld2 = __shfl_sync(FULLMASK, mydiag4, b4 + 2);
        const float Ld3 = __shfl_sync(FULLMASK, mydiag4, b4 + 3);
        const float L10 = __shfl_sync(FULLMASK, s4[0], b4 + 1);
        const float L20 = __shfl_sync(FULLMASK, s4[0], b4 + 2);
        const float L30 = __shfl_sync(FULLMASK, s4[0], b4 + 3);
        const float L21 = __shfl_sync(FULLMASK, s4[1], b4 + 2);
        const float L31 = __shfl_sync(FULLMASK, s4[1], b4 + 3);
        const float L32 = __shfl_sync(FULLMASK, s4[2], b4 + 3);

        // ==== K row o via two triangular solves (Pxy row via shuffle) ====
        float w0 = __shfl_sync(FULLMASK, pxy, o * 4 + 0);
        float w1 = __shfl_sync(FULLMASK, pxy, o * 4 + 1);
        float w2 = __shfl_sync(FULLMASK, pxy, o * 4 + 2);
        float w3 = __shfl_sync(FULLMASK, pxy, o * 4 + 3);
        w0 = w0 * d0;
        w1 = (w1 - L10 * w0) * d1;
        w2 = (w2 - L20 * w0 - L21 * w1) * d2;
        w3 = (w3 - L30 * w0 - L31 * w1 - L32 * w2) * d3;
        float z3 = w3 * d3;
        float z2 = (w2 - L32 * z3) * d2;
        float z1 = (w1 - L21 * z2 - L31 * z3) * d1;
        float z0 = (w0 - L10 * z1 - L20 * z2 - L30 * z3) * d0;

        // ==== innovation & state update ====
        float ypm = 0.0f;
        #pragma unroll
        for (int d = 0; d < 8; ++d)
            ypm += hmr[d] * __shfl_sync(FULLMASK, xpred, d);
        float inno = yy[((long)b * T + t) * 4 + m] - ypm;
        const float in0 = __shfl_sync(FULLMASK, inno, b4 + 0);
        const float in1 = __shfl_sync(FULLMASK, inno, b4 + 1);
        const float in2 = __shfl_sync(FULLMASK, inno, b4 + 2);
        const float in3 = __shfl_sync(FULLMASK, inno, b4 + 3);
        float xn = xpred + z0 * in0 + z1 * in1 + z2 * in2 + z3 * in3;
        xreg = xn;
        if (lane < 8) outX[((long)b * T + t) * 8 + o] = xn;

        // ==== U = K * L(Sy), P_new = Ppred - U U^T + JIT*I (bitwise symmetric) ====
        float U0 = z0 * Ld0 + z1 * L10 + z2 * L20 + z3 * L30;
        float U1 = z1 * Ld1 + z2 * L21 + z3 * L31;
        float U2 = z2 * Ld2 + z3 * L32;
        float U3 = z3 * Ld3;
        float Ua0 = __shfl_sync(FULLMASK, U0, q);
        float Ua1 = __shfl_sync(FULLMASK, U1, q);
        float Ua2 = __shfl_sync(FULLMASK, U2, q);
        float Ua3 = __shfl_sync(FULLMASK, U3, q);
        float Ub0 = __shfl_sync(FULLMASK, U0, q + 4);
        float Ub1 = __shfl_sync(FULLMASK, U1, q + 4);
        float Ub2 = __shfl_sync(FULLMASK, U2, q + 4);
        float Ub3 = __shfl_sync(FULLMASK, U3, q + 4);
        float p1 = ppa - (Ua0 * U0 + Ua1 * U1 + Ua2 * U2 + Ua3 * U3) + ((i1 == o) ? JIT : 0.0f);
        float p2 = ppb - (Ub0 * U0 + Ub1 * U1 + Ub2 * U2 + Ub3 * U3) + ((i2 == o) ? JIT : 0.0f);
        sP[i1 * 9 + o] = p1;
        sP[i2 * 9 + o] = p2;
        long bp = ((long)b * T + t) * 64;
        outP[bp + i1 * 8 + o] = p1;
        outP[bp + i2 * 8 + o] = p2;
        __syncwarp();
    }

    // ==== epilogue: q_e[T-1] from final P_pred ====
    {
        float a[8];
        #pragma unroll
        for (int c = 0; c < 8; ++c) a[c] = sPp[o * 9 + c];
        float md = 1.0f;
        #pragma unroll
        for (int k = 0; k < 8; ++k) {
            float akk = __shfl_sync(FULLMASK, a[k], k);
            float inv = rsqrtf(akk);
            float lk = a[k] * inv;
            if (o == k) { a[k] = akk * inv; md = a[k]; }
            else if (o > k) a[k] = lk;
            #pragma unroll
            for (int jj = k + 1; jj < 8; ++jj) {
                float lj = __shfl_sync(FULLMASK, a[k], jj);
                if (o >= jj) a[jj] -= a[k] * lj;
            }
        }
        float lg = __logf(md);
        lg += __shfl_xor_sync(FULLMASK, lg, 1);
        lg += __shfl_xor_sync(FULLMASK, lg, 2);
        lg += __shfl_xor_sync(FULLMASK, lg, 4);
        if (lane == 0) outQ[(long)b * T + (T - 1)] = lg;
    }
}

extern "C" void kernel_launch(void* const* d_in, const int* in_sizes, int n_in,
                              void* d_out, int out_size) {
    const float* X0  = (const float*)d_in[0];
    const float* u   = (const float*)d_in[1];
    const float* yv  = (const float*)d_in[2];
    const float* W1  = (const float*)d_in[3];
    const float* b1  = (const float*)d_in[4];
    const float* W2  = (const float*)d_in[5];
    const float* b2  = (const float*)d_in[6];
    const float* Hm  = (const float*)d_in[7];
    const float* lq  = (const float*)d_in[8];
    const float* lr  = (const float*)d_in[9];
    const float* lp0 = (const float*)d_in[10];

    const int B = in_sizes[0] / 8;                 // 1024
    const int T = in_sizes[1] / (B * 2);           // 256

    float* out  = (float*)d_out;
    float* outX = out;
    float* outP = out + (long)B * T * 8;
    float* outQ = out + (long)B * T * (8 + 64);
    float* outR = outQ + (long)B * T;

    ukf_kernel<<<B, 32>>>(X0, u, yv, W1, b1, W2, b2, Hm, lq, lr, lp0,
                          outX, outP, outQ, outR, T);
}